// round 13
// baseline (speedup 1.0000x reference)
#include <cuda_runtime.h>
#include <cuda_fp16.h>
#include <stdint.h>

typedef uint32_t u32;
typedef unsigned long long u64t;

// Problem constants
#define Nb   4
#define VQn  4096
#define VKn  4096
#define Cdim 128
#define Hdim 64

#define LOG2E 1.44269504f
#define KSPLIT 4

// ---------------- scratch (static device globals) ----------------------------
__device__ __align__(128) __half g_q[(size_t)Nb * VQn * Hdim];   // pre-scaled by 0.125*log2e
__device__ __align__(128) __half g_k[(size_t)Nb * VKn * Hdim];
__device__ __align__(128) __half g_vt[(size_t)Nb * Cdim * VKn];  // V^T[n][dv][key]
// key-split partials: O [KSPLIT][Nb*VQn][128] fp32, l [KSPLIT][Nb*VQn]
#define QO_ELEMS ((size_t)Nb * VQn * Cdim)   // 2,097,152
__device__ __align__(128) float g_op[KSPLIT * QO_ELEMS];
__device__ __align__(128) float g_lp[KSPLIT * (size_t)Nb * VQn];

// ---------------- helpers ----------------------------------------------------
__device__ __forceinline__ u32 s2u(const void* p) {
    u32 a;
    asm("{ .reg .u64 t; cvta.to.shared.u64 t, %1; cvt.u32.u64 %0, t; }"
        : "=r"(a) : "l"(p));
    return a;
}
__device__ __forceinline__ void cp16(u32 dst, const void* src) {
    asm volatile("cp.async.cg.shared.global [%0], [%1], 16;"
                 :: "r"(dst), "l"(src) : "memory");
}
__device__ __forceinline__ void cp_commit() {
    asm volatile("cp.async.commit_group;" ::: "memory");
}
template <int N>
__device__ __forceinline__ void cp_wait() {
    asm volatile("cp.async.wait_group %0;" :: "n"(N) : "memory");
}
__device__ __forceinline__ u32 pk(float lo, float hi) {
    u32 d;
    asm("cvt.rn.f16x2.f32 %0, %1, %2;" : "=r"(d) : "f"(hi), "f"(lo));
    return d;
}
__device__ __forceinline__ void ldsm4(u32& r0, u32& r1, u32& r2, u32& r3, u32 a) {
    asm volatile("ldmatrix.sync.aligned.m8n8.x4.shared.b16 {%0,%1,%2,%3}, [%4];"
                 : "=r"(r0), "=r"(r1), "=r"(r2), "=r"(r3) : "r"(a));
}
__device__ __forceinline__ void ldsm4t(u32& r0, u32& r1, u32& r2, u32& r3, u32 a) {
    asm volatile("ldmatrix.sync.aligned.m8n8.x4.trans.shared.b16 {%0,%1,%2,%3}, [%4];"
                 : "=r"(r0), "=r"(r1), "=r"(r2), "=r"(r3) : "r"(a));
}
__device__ __forceinline__ void mma16816(float* d, u32 a0, u32 a1, u32 a2, u32 a3,
                                         u32 b0, u32 b1) {
    asm volatile(
        "mma.sync.aligned.m16n8k16.row.col.f32.f16.f16.f32 "
        "{%0,%1,%2,%3}, {%4,%5,%6,%7}, {%8,%9}, {%0,%1,%2,%3};"
        : "+f"(d[0]), "+f"(d[1]), "+f"(d[2]), "+f"(d[3])
        : "r"(a0), "r"(a1), "r"(a2), "r"(a3), "r"(b0), "r"(b1));
}
__device__ __forceinline__ float fexp2(float s) {
    float r;
    asm("ex2.approx.f32 %0, %1;" : "=f"(r) : "f"(fminf(s, 20.f)));
    return r;
}
__device__ __forceinline__ void sts128(u32 addr, u32 a, u32 b, u32 c, u32 d) {
    asm volatile("st.shared.v4.b32 [%0], {%1,%2,%3,%4};"
                 :: "r"(addr), "r"(a), "r"(b), "r"(c), "r"(d) : "memory");
}

// ---------------- projections via mma.sync (round-10 winner, unchanged) ------
#define PTHREADS 256
#define PROWS    128
#define SM_A(c)    ((c) * 16384)            // 2 chunks x 16KB
#define PSM_W(c)   (32768 + (c) * 16384)    // H/64 chunks x 16KB
#define PSMEM_TOTAL 65536
#define BSTB 272                             // V bounce row stride (bytes)

template <int H, bool TRANSOUT>
__device__ __forceinline__ void proj_mma_body(
    const float* __restrict__ A, const float* __restrict__ W,
    __half* __restrict__ o, float scale, char* smx) {
    const u32 sb = s2u(smx);
    const int tid  = threadIdx.x;
    const int wid  = tid >> 5;
    const int lane = tid & 31;
    const int r0 = blockIdx.x * PROWS;

    // ---- A tile: fp32 -> fp16, swizzled smem [2][128 rows][64 halfs] ----
#pragma unroll
    for (int it = 0; it < 8; it++) {
        int g = tid + it * PTHREADS;
        int r = g >> 4;
        int k0 = (g & 15) * 8;
        const float* src = A + (size_t)(r0 + r) * 128 + k0;
        float4 v0 = *(const float4*)src;
        float4 v1 = *(const float4*)(src + 4);
        int ch = k0 >> 6, gran = (k0 & 63) >> 3;
        u32 addr = sb + SM_A(ch) + (u32)r * 128 + (u32)((gran ^ (r & 7)) << 4);
        sts128(addr, pk(v0.x, v0.y), pk(v0.z, v0.w), pk(v1.x, v1.y), pk(v1.z, v1.w));
    }
    // ---- W tile: fp32 -> fp16, NATURAL [k][h] layout, fully coalesced ----
    {
        constexpr int WGRAN = H / 8;
#pragma unroll
        for (int it = 0; it < (128 * WGRAN) / PTHREADS; it++) {
            int g = tid + it * PTHREADS;
            int kr = g / WGRAN;
            int hg = g % WGRAN;
            const float* src = W + (size_t)kr * H + hg * 8;
            float4 v0 = *(const float4*)src;
            float4 v1 = *(const float4*)(src + 4);
            int ch = hg >> 3, gran = hg & 7;
            u32 addr = sb + PSM_W(ch) + (u32)kr * 128 + (u32)((gran ^ (kr & 7)) << 4);
            sts128(addr, pk(v0.x, v0.y), pk(v0.z, v0.w), pk(v1.x, v1.y), pk(v1.z, v1.w));
        }
    }
    __syncthreads();

    const u32 l7 = lane & 7;
    const u32 rowA = (l7 + 8 * ((lane >> 3) & 1)) * 128;
    const u32 bitA = (lane >> 4) & 1;
    const u32 browk = (l7 + 8 * ((lane >> 3) & 1)) * 128;
    const u32 bbit  = (lane >> 4) & 1;

    float c[H / 8][4];
#pragma unroll
    for (int j = 0; j < H / 8; j++)
#pragma unroll
        for (int q = 0; q < 4; q++) c[j][q] = 0.f;

#pragma unroll
    for (int ks = 0; ks < 8; ks++) {
        const int ch = ks >> 2, kk = ks & 3;
        const u32 cszA = (((2 * kk + bitA) ^ l7) << 4);
        u32 a0, a1, a2, a3;
        ldsm4(a0, a1, a2, a3, sb + SM_A(ch) + (u32)(wid * 16) * 128 + rowA + cszA);
        const u32 wrowbase = (u32)(ks * 16) * 128 + browk;
#pragma unroll
        for (int np = 0; np < H / 16; np++) {
            const int wch = (np * 16) >> 6;
            const u32 gb = (u32)((2 * np) & 7) + bbit;
            u32 b0, b1, b2, b3;
            ldsm4t(b0, b1, b2, b3,
                   sb + PSM_W(wch) + wrowbase + ((gb ^ l7) << 4));
            mma16816(c[2 * np],     a0, a1, a2, a3, b0, b1);
            mma16816(c[2 * np + 1], a0, a1, a2, a3, b2, b3);
        }
    }

    if (!TRANSOUT) {
        const int grow = r0 + wid * 16 + (lane >> 2);
        const int cb = 2 * (lane & 3);
#pragma unroll
        for (int j = 0; j < H / 8; j++) {
            *(u32*)(o + (size_t)grow * H + 8 * j + cb) =
                pk(c[j][0] * scale, c[j][1] * scale);
            *(u32*)(o + (size_t)(grow + 8) * H + 8 * j + cb) =
                pk(c[j][2] * scale, c[j][3] * scale);
        }
    } else {
        __syncthreads();
        const int kr = wid * 16 + (lane >> 2);
        const int cb = 2 * (lane & 3);
#pragma unroll
        for (int j = 0; j < H / 8; j++) {
            *(u32*)(smx + kr * BSTB + (8 * j + cb) * 2) = pk(c[j][0], c[j][1]);
            *(u32*)(smx + (kr + 8) * BSTB + (8 * j + cb) * 2) = pk(c[j][2], c[j][3]);
        }
        __syncthreads();
        const int dv = tid >> 1;
        const int kh = tid & 1;
        const int nB = r0 >> 12;
        const int key0 = (r0 & 4095) + kh * 64;
        u32 buf[32];
#pragma unroll
        for (int i = 0; i < 32; i++) {
            u32 lo = *(const unsigned short*)(smx + (kh * 64 + 2 * i) * BSTB + dv * 2);
            u32 hi = *(const unsigned short*)(smx + (kh * 64 + 2 * i + 1) * BSTB + dv * 2);
            buf[i] = lo | (hi << 16);
        }
        __half* dst = o + ((size_t)nB * 128 + dv) * 4096 + key0;
#pragma unroll
        for (int w = 0; w < 8; w++)
            *(uint4*)(dst + 8 * w) = make_uint4(buf[4 * w], buf[4 * w + 1],
                                                buf[4 * w + 2], buf[4 * w + 3]);
    }
}

__global__ __launch_bounds__(PTHREADS)
void proj_mma(const float* __restrict__ x, const float* __restrict__ y,
              const float* __restrict__ Wq, const float* __restrict__ Wk,
              const float* __restrict__ Wv,
              __half* __restrict__ q, __half* __restrict__ k,
              __half* __restrict__ vt) {
    extern __shared__ char smx[];
    const int task = blockIdx.y;
    if (task == 0)      proj_mma_body<64, false>(x, Wq, q, 0.125f * LOG2E, smx);
    else if (task == 1) proj_mma_body<64, false>(y, Wk, k, 1.0f, smx);
    else                proj_mma_body<128, true>(y, Wv, vt, 1.0f, smx);
}

// ------- flash attention: 128 thr, 4 warps x M=32, 4-way key-split grid ------
#define BM  128
#define BN  64
#define NTILES (VKn / BN / KSPLIT)   // 16 tiles per key-quarter
#define FTHREADS 128

#define SM_Q       0
#define SM_KS(s)   (16384 + (s) * 24576)
#define SM_VS(s)   (SM_KS(s) + 8192)
#define SMEM_TOTAL 90112

__device__ __forceinline__ void load_kv(u32 sb, int stage, const char* kB,
                                        const char* vB, int kt, int tid) {
    const size_t krow = (size_t)kt * BN;
    const u32 kdst = sb + SM_KS(stage);
#pragma unroll
    for (int it = 0; it < 4; it++) {
        int i = tid + it * FTHREADS;
        u32 r = i >> 3, c = i & 7;
        cp16(kdst + r * 128 + ((c ^ (r & 7)) << 4), kB + (krow + r) * 128 + c * 16);
    }
    const u32 vdst = sb + SM_VS(stage);
#pragma unroll
    for (int it = 0; it < 8; it++) {
        int i = tid + it * FTHREADS;
        u32 r = i >> 3, c = i & 7;
        cp16(vdst + r * 128 + ((c ^ (r & 7)) << 4),
             vB + (size_t)r * 8192 + krow * 2 + c * 16);
    }
    cp_commit();
}

__global__ __launch_bounds__(FTHREADS, 2)
void flash_mma(const __half* __restrict__ Q, const __half* __restrict__ K,
               const __half* __restrict__ VT,
               float* __restrict__ opart, float* __restrict__ lpart) {
    extern __shared__ char smx[];
    const u32 sb = s2u(smx);
    const int tid  = threadIdx.x;
    const int wg   = tid >> 5;
    const int lane = tid & 31;
    const int n     = blockIdx.y;
    const int q0    = blockIdx.x * BM;
    const int khalf = blockIdx.z;
    const int kt0   = khalf * NTILES;

    const char* qB = (const char*)(Q + ((size_t)n * VQn + q0) * Hdim);
    const char* kB = (const char*)(K + (size_t)n * VKn * Hdim);
    const char* vB = (const char*)(VT + (size_t)n * Cdim * VKn);

#pragma unroll
    for (int it = 0; it < 8; it++) {
        int i = tid + it * FTHREADS;
        u32 r = i >> 3, c = i & 7;
        cp16(sb + SM_Q + r * 128 + ((c ^ (r & 7)) << 4), qB + r * 128 + c * 16);
    }
    cp_commit();
    load_kv(sb, 0, kB, vB, kt0, tid);
    load_kv(sb, 1, kB, vB, kt0 + 1, tid);
    cp_wait<1>();
    __syncthreads();

    const u32 l7 = lane & 7;
    const u32 rowA = (l7 + 8 * ((lane >> 3) & 1)) * 128;
    const u32 rowB = (l7 + 8 * ((lane >> 4) & 1)) * 128;
    const u32 bitA = (lane >> 4) & 1;
    const u32 bitB = (lane >> 3) & 1;
    u32 cswzA[4], cswzB[4];
#pragma unroll
    for (int kk = 0; kk < 4; kk++) {
        cswzA[kk] = (((2 * kk + bitA) ^ l7) << 4);
        cswzB[kk] = (((2 * kk + bitB) ^ l7) << 4);
    }

    u32 qf[4][8];
    {
        const u32 qb0 = sb + SM_Q + (u32)(wg * 32) * 128 + rowA;
#pragma unroll
        for (int kk = 0; kk < 4; kk++) {
            ldsm4(qf[kk][0], qf[kk][1], qf[kk][2], qf[kk][3], qb0 + cswzA[kk]);
            ldsm4(qf[kk][4], qf[kk][5], qf[kk][6], qf[kk][7], qb0 + 2048 + cswzA[kk]);
        }
    }

    float oacc[2][16][4];
#pragma unroll
    for (int m = 0; m < 2; m++)
#pragma unroll
        for (int v = 0; v < 16; v++)
#pragma unroll
            for (int c = 0; c < 4; c++) oacc[m][v][c] = 0.f;
    float lr[4] = {0.f, 0.f, 0.f, 0.f};

    for (int it = 0; it < NTILES; it++) {
        const int st = it % 3;
        if (it + 1 < NTILES) cp_wait<1>(); else cp_wait<0>();
        __syncthreads();
        if (it + 2 < NTILES) load_kv(sb, (it + 2) % 3, kB, vB, kt0 + it + 2, tid);

        u32 paf[4][8];
        const u32 kbase = sb + SM_KS(st) + rowB;
#pragma unroll
        for (int jp = 0; jp < 4; jp++) {
            float s00[4] = {0.f,0.f,0.f,0.f}, s01[4] = {0.f,0.f,0.f,0.f};
            float s10[4] = {0.f,0.f,0.f,0.f}, s11[4] = {0.f,0.f,0.f,0.f};
#pragma unroll
            for (int kk = 0; kk < 4; kk++) {
                u32 b0, b1, b2, b3;
                ldsm4(b0, b1, b2, b3, kbase + jp * 2048 + cswzB[kk]);
                mma16816(s00, qf[kk][0], qf[kk][1], qf[kk][2], qf[kk][3], b0, b1);
                mma16816(s01, qf[kk][0], qf[kk][1], qf[kk][2], qf[kk][3], b2, b3);
                mma16816(s10, qf[kk][4], qf[kk][5], qf[kk][6], qf[kk][7], b0, b1);
                mma16816(s11, qf[kk][4], qf[kk][5], qf[kk][6], qf[kk][7], b2, b3);
            }
            float e000 = fexp2(s00[0]), e001 = fexp2(s00[1]);
            float e002 = fexp2(s00[2]), e003 = fexp2(s00[3]);
            float e010 = fexp2(s01[0]), e011 = fexp2(s01[1]);
            float e012 = fexp2(s01[2]), e013 = fexp2(s01[3]);
            lr[0] += e000 + e001 + e010 + e011;
            lr[1] += e002 + e003 + e012 + e013;
            paf[jp][0] = pk(e000, e001);
            paf[jp][1] = pk(e002, e003);
            paf[jp][2] = pk(e010, e011);
            paf[jp][3] = pk(e012, e013);
            float e100 = fexp2(s10[0]), e101 = fexp2(s10[1]);
            float e102 = fexp2(s10[2]), e103 = fexp2(s10[3]);
            float e110 = fexp2(s11[0]), e111 = fexp2(s11[1]);
            float e112 = fexp2(s11[2]), e113 = fexp2(s11[3]);
            lr[2] += e100 + e101 + e110 + e111;
            lr[3] += e102 + e103 + e112 + e113;
            paf[jp][4] = pk(e100, e101);
            paf[jp][5] = pk(e102, e103);
            paf[jp][6] = pk(e110, e111);
            paf[jp][7] = pk(e112, e113);
        }

        const u32 vbase = sb + SM_VS(st) + rowB;
#pragma unroll
        for (int nvp = 0; nvp < 8; nvp++)
#pragma unroll
            for (int kk = 0; kk < 4; kk++) {
                u32 b0, b1, b2, b3;
                ldsm4(b0, b1, b2, b3, vbase + nvp * 2048 + cswzB[kk]);
                mma16816(oacc[0][2 * nvp],
                         paf[kk][0], paf[kk][1], paf[kk][2], paf[kk][3], b0, b1);
                mma16816(oacc[0][2 * nvp + 1],
                         paf[kk][0], paf[kk][1], paf[kk][2], paf[kk][3], b2, b3);
                mma16816(oacc[1][2 * nvp],
                         paf[kk][4], paf[kk][5], paf[kk][6], paf[kk][7], b0, b1);
                mma16816(oacc[1][2 * nvp + 1],
                         paf[kk][4], paf[kk][5], paf[kk][6], paf[kk][7], b2, b3);
            }
    }

#pragma unroll
    for (int d = 1; d < 4; d <<= 1)
#pragma unroll
        for (int i = 0; i < 4; i++)
            lr[i] += __shfl_xor_sync(0xffffffffu, lr[i], d);

    float* opb = opart + (size_t)khalf * QO_ELEMS;
    float* lpb = lpart + (size_t)khalf * (Nb * VQn);
    const int cl = 2 * (lane & 3);
#pragma unroll
    for (int m = 0; m < 2; m++) {
        const int gr = q0 + wg * 32 + m * 16 + (lane >> 2);
        const size_t rowg = (size_t)n * VQn + gr;
        if ((lane & 3) == 0) {
            lpb[rowg]     = lr[2 * m];
            lpb[rowg + 8] = lr[2 * m + 1];
        }
#pragma unroll
        for (int v = 0; v < 16; v++) {
            *(float2*)&opb[rowg * 128 + v * 8 + cl] =
                make_float2(oacc[m][v][0], oacc[m][v][1]);
            *(float2*)&opb[(rowg + 8) * 128 + v * 8 + cl] =
                make_float2(oacc[m][v][2], oacc[m][v][3]);
        }
    }
}

// ---------------- combine: out = sum(O_i) / sum(l_i) --------------------------
__global__ __launch_bounds__(256)
void combine(const float* __restrict__ opart, const float* __restrict__ lpart,
             float* __restrict__ out) {
    const size_t i = (size_t)blockIdx.x * 256 + threadIdx.x;
    const size_t row = i >> 5;
    float lsum = 0.f;
#pragma unroll
    for (int s = 0; s < KSPLIT; s++)
        lsum += lpart[(size_t)s * (Nb * VQn) + row];
    const float inv = 1.f / lsum;
    float4 o = make_float4(0.f, 0.f, 0.f, 0.f);
#pragma unroll
    for (int s = 0; s < KSPLIT; s++) {
        float4 a = *(const float4*)(opart + (size_t)s * QO_ELEMS + 4 * i);
        o.x += a.x; o.y += a.y; o.z += a.z; o.w += a.w;
    }
    o.x *= inv; o.y *= inv; o.z *= inv; o.w *= inv;
    *(float4*)(out + 4 * i) = o;
}

// ---------------- launch ------------------------------------------------------
extern "C" void kernel_launch(void* const* d_in, const int* in_sizes, int n_in,
                              void* d_out, int out_size) {
    (void)in_sizes; (void)n_in; (void)out_size;
    const float* x  = (const float*)d_in[0];
    const float* y  = (const float*)d_in[1];
    const float* Wq = (const float*)d_in[2];
    const float* Wk = (const float*)d_in[3];
    const float* Wv = (const float*)d_in[4];
    float* out = (float*)d_out;

    __half *qp, *kp, *vtp;
    float *opp, *lpp;
    cudaGetSymbolAddress((void**)&qp, g_q);
    cudaGetSymbolAddress((void**)&kp, g_k);
    cudaGetSymbolAddress((void**)&vtp, g_vt);
    cudaGetSymbolAddress((void**)&opp, g_op);
    cudaGetSymbolAddress((void**)&lpp, g_lp);

    cudaFuncSetAttribute(proj_mma,
                         cudaFuncAttributeMaxDynamicSharedMemorySize, PSMEM_TOTAL);
    cudaFuncSetAttribute(flash_mma,
                         cudaFuncAttributeMaxDynamicSharedMemorySize, SMEM_TOTAL);

    dim3 pgrid(Nb * VQn / PROWS, 3);
    proj_mma<<<pgrid, PTHREADS, PSMEM_TOTAL>>>(x, y, Wq, Wk, Wv, qp, kp, vtp);

    dim3 grid(VQn / BM, Nb, KSPLIT);
    flash_mma<<<grid, FTHREADS, SMEM_TOTAL>>>(qp, kp, vtp, opp, lpp);

    combine<<<(int)(QO_ELEMS / 4 / 256), 256>>>(opp, lpp, out);
}

// round 14
// speedup vs baseline: 1.0428x; 1.0428x over previous
#include <cuda_runtime.h>
#include <cuda_fp16.h>
#include <stdint.h>

typedef uint32_t u32;
typedef unsigned long long u64t;

// Problem constants
#define Nb   4
#define VQn  4096
#define VKn  4096
#define Cdim 128
#define Hdim 64

#define LOG2E 1.44269504f

// ---------------- scratch (static device globals) ----------------------------
__device__ __align__(128) __half g_q[(size_t)Nb * VQn * Hdim];   // pre-scaled by 0.125*log2e
__device__ __align__(128) __half g_k[(size_t)Nb * VKn * Hdim];
__device__ __align__(128) __half g_vt[(size_t)Nb * Cdim * VKn];  // V^T[n][dv][key]
// key-split partials: O [2][Nb*VQn][128] fp32, l [2][Nb*VQn]
#define HALF_ELEMS ((size_t)Nb * VQn * Cdim)   // 2,097,152
__device__ __align__(128) float g_op[2 * HALF_ELEMS];
__device__ __align__(128) float g_lp[2 * (size_t)Nb * VQn];

// ---------------- helpers ----------------------------------------------------
__device__ __forceinline__ u32 s2u(const void* p) {
    u32 a;
    asm("{ .reg .u64 t; cvta.to.shared.u64 t, %1; cvt.u32.u64 %0, t; }"
        : "=r"(a) : "l"(p));
    return a;
}
__device__ __forceinline__ void cp16(u32 dst, const void* src) {
    asm volatile("cp.async.cg.shared.global [%0], [%1], 16;"
                 :: "r"(dst), "l"(src) : "memory");
}
__device__ __forceinline__ void cp_commit() {
    asm volatile("cp.async.commit_group;" ::: "memory");
}
template <int N>
__device__ __forceinline__ void cp_wait() {
    asm volatile("cp.async.wait_group %0;" :: "n"(N) : "memory");
}
__device__ __forceinline__ u32 pk(float lo, float hi) {
    u32 d;
    asm("cvt.rn.f16x2.f32 %0, %1, %2;" : "=r"(d) : "f"(hi), "f"(lo));
    return d;
}
__device__ __forceinline__ void ldsm4(u32& r0, u32& r1, u32& r2, u32& r3, u32 a) {
    asm volatile("ldmatrix.sync.aligned.m8n8.x4.shared.b16 {%0,%1,%2,%3}, [%4];"
                 : "=r"(r0), "=r"(r1), "=r"(r2), "=r"(r3) : "r"(a));
}
__device__ __forceinline__ void ldsm4t(u32& r0, u32& r1, u32& r2, u32& r3, u32 a) {
    asm volatile("ldmatrix.sync.aligned.m8n8.x4.trans.shared.b16 {%0,%1,%2,%3}, [%4];"
                 : "=r"(r0), "=r"(r1), "=r"(r2), "=r"(r3) : "r"(a));
}
__device__ __forceinline__ void mma16816(float* d, u32 a0, u32 a1, u32 a2, u32 a3,
                                         u32 b0, u32 b1) {
    asm volatile(
        "mma.sync.aligned.m16n8k16.row.col.f32.f16.f16.f32 "
        "{%0,%1,%2,%3}, {%4,%5,%6,%7}, {%8,%9}, {%0,%1,%2,%3};"
        : "+f"(d[0]), "+f"(d[1]), "+f"(d[2]), "+f"(d[3])
        : "r"(a0), "r"(a1), "r"(a2), "r"(a3), "r"(b0), "r"(b1));
}
__device__ __forceinline__ float fexp2(float s) {
    float r;
    asm("ex2.approx.f32 %0, %1;" : "=f"(r) : "f"(fminf(s, 20.f)));
    return r;
}
__device__ __forceinline__ void sts128(u32 addr, u32 a, u32 b, u32 c, u32 d) {
    asm volatile("st.shared.v4.b32 [%0], {%1,%2,%3,%4};"
                 :: "r"(addr), "r"(a), "r"(b), "r"(c), "r"(d) : "memory");
}

// ---------------- projections via mma.sync (round-10 winner, unchanged) ------
#define PTHREADS 256
#define PROWS    128
#define SM_A(c)    ((c) * 16384)            // 2 chunks x 16KB
#define PSM_W(c)   (32768 + (c) * 16384)    // H/64 chunks x 16KB
#define PSMEM_TOTAL 65536
#define BSTB 272                             // V bounce row stride (bytes)

template <int H, bool TRANSOUT>
__device__ __forceinline__ void proj_mma_body(
    const float* __restrict__ A, const float* __restrict__ W,
    __half* __restrict__ o, float scale, char* smx) {
    const u32 sb = s2u(smx);
    const int tid  = threadIdx.x;
    const int wid  = tid >> 5;
    const int lane = tid & 31;
    const int r0 = blockIdx.x * PROWS;

    // ---- A tile: fp32 -> fp16, swizzled smem [2][128 rows][64 halfs] ----
#pragma unroll
    for (int it = 0; it < 8; it++) {
        int g = tid + it * PTHREADS;
        int r = g >> 4;
        int k0 = (g & 15) * 8;
        const float* src = A + (size_t)(r0 + r) * 128 + k0;
        float4 v0 = *(const float4*)src;
        float4 v1 = *(const float4*)(src + 4);
        int ch = k0 >> 6, gran = (k0 & 63) >> 3;
        u32 addr = sb + SM_A(ch) + (u32)r * 128 + (u32)((gran ^ (r & 7)) << 4);
        sts128(addr, pk(v0.x, v0.y), pk(v0.z, v0.w), pk(v1.x, v1.y), pk(v1.z, v1.w));
    }
    // ---- W tile: fp32 -> fp16, NATURAL [k][h] layout, fully coalesced ----
    {
        constexpr int WGRAN = H / 8;
#pragma unroll
        for (int it = 0; it < (128 * WGRAN) / PTHREADS; it++) {
            int g = tid + it * PTHREADS;
            int kr = g / WGRAN;
            int hg = g % WGRAN;
            const float* src = W + (size_t)kr * H + hg * 8;
            float4 v0 = *(const float4*)src;
            float4 v1 = *(const float4*)(src + 4);
            int ch = hg >> 3, gran = hg & 7;
            u32 addr = sb + PSM_W(ch) + (u32)kr * 128 + (u32)((gran ^ (kr & 7)) << 4);
            sts128(addr, pk(v0.x, v0.y), pk(v0.z, v0.w), pk(v1.x, v1.y), pk(v1.z, v1.w));
        }
    }
    __syncthreads();

    const u32 l7 = lane & 7;
    const u32 rowA = (l7 + 8 * ((lane >> 3) & 1)) * 128;
    const u32 bitA = (lane >> 4) & 1;
    const u32 browk = (l7 + 8 * ((lane >> 3) & 1)) * 128;
    const u32 bbit  = (lane >> 4) & 1;

    float c[H / 8][4];
#pragma unroll
    for (int j = 0; j < H / 8; j++)
#pragma unroll
        for (int q = 0; q < 4; q++) c[j][q] = 0.f;

#pragma unroll
    for (int ks = 0; ks < 8; ks++) {
        const int ch = ks >> 2, kk = ks & 3;
        const u32 cszA = (((2 * kk + bitA) ^ l7) << 4);
        u32 a0, a1, a2, a3;
        ldsm4(a0, a1, a2, a3, sb + SM_A(ch) + (u32)(wid * 16) * 128 + rowA + cszA);
        const u32 wrowbase = (u32)(ks * 16) * 128 + browk;
#pragma unroll
        for (int np = 0; np < H / 16; np++) {
            const int wch = (np * 16) >> 6;
            const u32 gb = (u32)((2 * np) & 7) + bbit;
            u32 b0, b1, b2, b3;
            ldsm4t(b0, b1, b2, b3,
                   sb + PSM_W(wch) + wrowbase + ((gb ^ l7) << 4));
            mma16816(c[2 * np],     a0, a1, a2, a3, b0, b1);
            mma16816(c[2 * np + 1], a0, a1, a2, a3, b2, b3);
        }
    }

    if (!TRANSOUT) {
        const int grow = r0 + wid * 16 + (lane >> 2);
        const int cb = 2 * (lane & 3);
#pragma unroll
        for (int j = 0; j < H / 8; j++) {
            *(u32*)(o + (size_t)grow * H + 8 * j + cb) =
                pk(c[j][0] * scale, c[j][1] * scale);
            *(u32*)(o + (size_t)(grow + 8) * H + 8 * j + cb) =
                pk(c[j][2] * scale, c[j][3] * scale);
        }
    } else {
        __syncthreads();
        const int kr = wid * 16 + (lane >> 2);
        const int cb = 2 * (lane & 3);
#pragma unroll
        for (int j = 0; j < H / 8; j++) {
            *(u32*)(smx + kr * BSTB + (8 * j + cb) * 2) = pk(c[j][0], c[j][1]);
            *(u32*)(smx + (kr + 8) * BSTB + (8 * j + cb) * 2) = pk(c[j][2], c[j][3]);
        }
        __syncthreads();
        const int dv = tid >> 1;
        const int kh = tid & 1;
        const int nB = r0 >> 12;
        const int key0 = (r0 & 4095) + kh * 64;
        u32 buf[32];
#pragma unroll
        for (int i = 0; i < 32; i++) {
            u32 lo = *(const unsigned short*)(smx + (kh * 64 + 2 * i) * BSTB + dv * 2);
            u32 hi = *(const unsigned short*)(smx + (kh * 64 + 2 * i + 1) * BSTB + dv * 2);
            buf[i] = lo | (hi << 16);
        }
        __half* dst = o + ((size_t)nB * 128 + dv) * 4096 + key0;
#pragma unroll
        for (int w = 0; w < 8; w++)
            *(uint4*)(dst + 8 * w) = make_uint4(buf[4 * w], buf[4 * w + 1],
                                                buf[4 * w + 2], buf[4 * w + 3]);
    }
}

__global__ __launch_bounds__(PTHREADS)
void proj_mma(const float* __restrict__ x, const float* __restrict__ y,
              const float* __restrict__ Wq, const float* __restrict__ Wk,
              const float* __restrict__ Wv,
              __half* __restrict__ q, __half* __restrict__ k,
              __half* __restrict__ vt) {
    extern __shared__ char smx[];
    const int task = blockIdx.y;
    if (task == 0)      proj_mma_body<64, false>(x, Wq, q, 0.125f * LOG2E, smx);
    else if (task == 1) proj_mma_body<64, false>(y, Wk, k, 1.0f, smx);
    else                proj_mma_body<128, true>(y, Wv, vt, 1.0f, smx);
}

// ------- flash attention: 128 thr, 4 warps x M=32, key-split grid ------------
// Round-10 winner with a 4-stage ring (prefetch distance 3, cp_wait<2>).
#define BM  128
#define BN  64
#define NTILES 32
#define FTHREADS 128

#define SM_Q       0
#define SM_KS(s)   (16384 + (s) * 24576)
#define SM_VS(s)   (SM_KS(s) + 8192)
#define SMEM_TOTAL 114688   // 16KB Q + 4 x 24KB stages; 2 CTAs = 224KB <= 228KB

__device__ __forceinline__ void load_kv(u32 sb, int stage, const char* kB,
                                        const char* vB, int kt, int tid) {
    const size_t krow = (size_t)kt * BN;
    const u32 kdst = sb + SM_KS(stage);
#pragma unroll
    for (int it = 0; it < 4; it++) {
        int i = tid + it * FTHREADS;
        u32 r = i >> 3, c = i & 7;
        cp16(kdst + r * 128 + ((c ^ (r & 7)) << 4), kB + (krow + r) * 128 + c * 16);
    }
    const u32 vdst = sb + SM_VS(stage);
#pragma unroll
    for (int it = 0; it < 8; it++) {
        int i = tid + it * FTHREADS;
        u32 r = i >> 3, c = i & 7;
        cp16(vdst + r * 128 + ((c ^ (r & 7)) << 4),
             vB + (size_t)r * 8192 + krow * 2 + c * 16);
    }
    cp_commit();
}

__global__ __launch_bounds__(FTHREADS, 2)
void flash_mma(const __half* __restrict__ Q, const __half* __restrict__ K,
               const __half* __restrict__ VT,
               float* __restrict__ opart, float* __restrict__ lpart) {
    extern __shared__ char smx[];
    const u32 sb = s2u(smx);
    const int tid  = threadIdx.x;
    const int wg   = tid >> 5;
    const int lane = tid & 31;
    const int n     = blockIdx.y;
    const int q0    = blockIdx.x * BM;
    const int khalf = blockIdx.z;
    const int kt0   = khalf * NTILES;

    const char* qB = (const char*)(Q + ((size_t)n * VQn + q0) * Hdim);
    const char* kB = (const char*)(K + (size_t)n * VKn * Hdim);
    const char* vB = (const char*)(VT + (size_t)n * Cdim * VKn);

    // prologue: Q (group 0), tiles kt0..kt0+2 (groups 1..3)
#pragma unroll
    for (int it = 0; it < 8; it++) {
        int i = tid + it * FTHREADS;
        u32 r = i >> 3, c = i & 7;
        cp16(sb + SM_Q + r * 128 + ((c ^ (r & 7)) << 4), qB + r * 128 + c * 16);
    }
    cp_commit();
    load_kv(sb, 0, kB, vB, kt0, tid);
    load_kv(sb, 1, kB, vB, kt0 + 1, tid);
    load_kv(sb, 2, kB, vB, kt0 + 2, tid);
    cp_wait<2>();          // Q + tile kt0 complete
    __syncthreads();

    const u32 l7 = lane & 7;
    const u32 rowA = (l7 + 8 * ((lane >> 3) & 1)) * 128;
    const u32 rowB = (l7 + 8 * ((lane >> 4) & 1)) * 128;
    const u32 bitA = (lane >> 4) & 1;
    const u32 bitB = (lane >> 3) & 1;
    u32 cswzA[4], cswzB[4];
#pragma unroll
    for (int kk = 0; kk < 4; kk++) {
        cswzA[kk] = (((2 * kk + bitA) ^ l7) << 4);
        cswzB[kk] = (((2 * kk + bitB) ^ l7) << 4);
    }

    u32 qf[4][8];
    {
        const u32 qb0 = sb + SM_Q + (u32)(wg * 32) * 128 + rowA;
#pragma unroll
        for (int kk = 0; kk < 4; kk++) {
            ldsm4(qf[kk][0], qf[kk][1], qf[kk][2], qf[kk][3], qb0 + cswzA[kk]);
            ldsm4(qf[kk][4], qf[kk][5], qf[kk][6], qf[kk][7], qb0 + 2048 + cswzA[kk]);
        }
    }

    float oacc[2][16][4];
#pragma unroll
    for (int m = 0; m < 2; m++)
#pragma unroll
        for (int v = 0; v < 16; v++)
#pragma unroll
            for (int c = 0; c < 4; c++) oacc[m][v][c] = 0.f;
    float lr[4] = {0.f, 0.f, 0.f, 0.f};

    for (int it = 0; it < NTILES; it++) {
        const int st = it & 3;
        if (it + 2 < NTILES) cp_wait<2>();
        else if (it + 1 < NTILES) cp_wait<1>();
        else cp_wait<0>();
        __syncthreads();   // stage st ready for all; stage (it+3)&3 free (read at it-1)
        if (it + 3 < NTILES) load_kv(sb, (it + 3) & 3, kB, vB, kt0 + it + 3, tid);

        u32 paf[4][8];
        const u32 kbase = sb + SM_KS(st) + rowB;
#pragma unroll
        for (int jp = 0; jp < 4; jp++) {
            float s00[4] = {0.f,0.f,0.f,0.f}, s01[4] = {0.f,0.f,0.f,0.f};
            float s10[4] = {0.f,0.f,0.f,0.f}, s11[4] = {0.f,0.f,0.f,0.f};
#pragma unroll
            for (int kk = 0; kk < 4; kk++) {
                u32 b0, b1, b2, b3;
                ldsm4(b0, b1, b2, b3, kbase + jp * 2048 + cswzB[kk]);
                mma16816(s00, qf[kk][0], qf[kk][1], qf[kk][2], qf[kk][3], b0, b1);
                mma16816(s01, qf[kk][0], qf[kk][1], qf[kk][2], qf[kk][3], b2, b3);
                mma16816(s10, qf[kk][4], qf[kk][5], qf[kk][6], qf[kk][7], b0, b1);
                mma16816(s11, qf[kk][4], qf[kk][5], qf[kk][6], qf[kk][7], b2, b3);
            }
            float e000 = fexp2(s00[0]), e001 = fexp2(s00[1]);
            float e002 = fexp2(s00[2]), e003 = fexp2(s00[3]);
            float e010 = fexp2(s01[0]), e011 = fexp2(s01[1]);
            float e012 = fexp2(s01[2]), e013 = fexp2(s01[3]);
            lr[0] += e000 + e001 + e010 + e011;
            lr[1] += e002 + e003 + e012 + e013;
            paf[jp][0] = pk(e000, e001);
            paf[jp][1] = pk(e002, e003);
            paf[jp][2] = pk(e010, e011);
            paf[jp][3] = pk(e012, e013);
            float e100 = fexp2(s10[0]), e101 = fexp2(s10[1]);
            float e102 = fexp2(s10[2]), e103 = fexp2(s10[3]);
            float e110 = fexp2(s11[0]), e111 = fexp2(s11[1]);
            float e112 = fexp2(s11[2]), e113 = fexp2(s11[3]);
            lr[2] += e100 + e101 + e110 + e111;
            lr[3] += e102 + e103 + e112 + e113;
            paf[jp][4] = pk(e100, e101);
            paf[jp][5] = pk(e102, e103);
            paf[jp][6] = pk(e110, e111);
            paf[jp][7] = pk(e112, e113);
        }

        const u32 vbase = sb + SM_VS(st) + rowB;
#pragma unroll
        for (int nvp = 0; nvp < 8; nvp++)
#pragma unroll
            for (int kk = 0; kk < 4; kk++) {
                u32 b0, b1, b2, b3;
                ldsm4(b0, b1, b2, b3, vbase + nvp * 2048 + cswzB[kk]);
                mma16816(oacc[0][2 * nvp],
                         paf[kk][0], paf[kk][1], paf[kk][2], paf[kk][3], b0, b1);
                mma16816(oacc[0][2 * nvp + 1],
                         paf[kk][0], paf[kk][1], paf[kk][2], paf[kk][3], b2, b3);
                mma16816(oacc[1][2 * nvp],
                         paf[kk][4], paf[kk][5], paf[kk][6], paf[kk][7], b0, b1);
                mma16816(oacc[1][2 * nvp + 1],
                         paf[kk][4], paf[kk][5], paf[kk][6], paf[kk][7], b2, b3);
            }
    }

#pragma unroll
    for (int d = 1; d < 4; d <<= 1)
#pragma unroll
        for (int i = 0; i < 4; i++)
            lr[i] += __shfl_xor_sync(0xffffffffu, lr[i], d);

    float* opb = opart + (size_t)khalf * HALF_ELEMS;
    float* lpb = lpart + (size_t)khalf * (Nb * VQn);
    const int cl = 2 * (lane & 3);
#pragma unroll
    for (int m = 0; m < 2; m++) {
        const int gr = q0 + wg * 32 + m * 16 + (lane >> 2);
        const size_t rowg = (size_t)n * VQn + gr;
        if ((lane & 3) == 0) {
            lpb[rowg]     = lr[2 * m];
            lpb[rowg + 8] = lr[2 * m + 1];
        }
#pragma unroll
        for (int v = 0; v < 16; v++) {
            *(float2*)&opb[rowg * 128 + v * 8 + cl] =
                make_float2(oacc[m][v][0], oacc[m][v][1]);
            *(float2*)&opb[(rowg + 8) * 128 + v * 8 + cl] =
                make_float2(oacc[m][v][2], oacc[m][v][3]);
        }
    }
}

// ---------------- combine: out = (O0+O1) / (l0+l1) ---------------------------
__global__ __launch_bounds__(256)
void combine(const float* __restrict__ opart, const float* __restrict__ lpart,
             float* __restrict__ out) {
    const size_t i = (size_t)blockIdx.x * 256 + threadIdx.x;
    const size_t row = i >> 5;
    const float inv = 1.f / (lpart[row] + lpart[(size_t)Nb * VQn + row]);
    float4 a = *(const float4*)(opart + 4 * i);
    float4 b = *(const float4*)(opart + HALF_ELEMS + 4 * i);
    float4 o;
    o.x = (a.x + b.x) * inv;
    o.y = (a.y + b.y) * inv;
    o.z = (a.z + b.z) * inv;
    o.w = (a.w + b.w) * inv;
    *(float4*)(out + 4 * i) = o;
}

// ---------------- launch ------------------------------------------------------
extern "C" void kernel_launch(void* const* d_in, const int* in_sizes, int n_in,
                              void* d_out, int out_size) {
    (void)in_sizes; (void)n_in; (void)out_size;
    const float* x  = (const float*)d_in[0];
    const float* y  = (const float*)d_in[1];
    const float* Wq = (const float*)d_in[2];
    const float* Wk = (const float*)d_in[3];
    const float* Wv = (const float*)d_in[4];
    float* out = (float*)d_out;

    __half *qp, *kp, *vtp;
    float *opp, *lpp;
    cudaGetSymbolAddress((void**)&qp, g_q);
    cudaGetSymbolAddress((void**)&kp, g_k);
    cudaGetSymbolAddress((void**)&vtp, g_vt);
    cudaGetSymbolAddress((void**)&opp, g_op);
    cudaGetSymbolAddress((void**)&lpp, g_lp);

    cudaFuncSetAttribute(proj_mma,
                         cudaFuncAttributeMaxDynamicSharedMemorySize, PSMEM_TOTAL);
    cudaFuncSetAttribute(flash_mma,
                         cudaFuncAttributeMaxDynamicSharedMemorySize, SMEM_TOTAL);

    dim3 pgrid(Nb * VQn / PROWS, 3);
    proj_mma<<<pgrid, PTHREADS, PSMEM_TOTAL>>>(x, y, Wq, Wk, Wv, qp, kp, vtp);

    dim3 grid(VQn / BM, Nb, 2);
    flash_mma<<<grid, FTHREADS, SMEM_TOTAL>>>(qp, kp, vtp, opp, lpp);

    combine<<<(int)(HALF_ELEMS / 4 / 256), 256>>>(opp, lpp, out);
}

// round 15
// speedup vs baseline: 1.0571x; 1.0137x over previous
#include <cuda_runtime.h>
#include <cuda_fp16.h>
#include <stdint.h>

typedef uint32_t u32;
typedef unsigned long long u64t;

// Problem constants
#define Nb   4
#define VQn  4096
#define VKn  4096
#define Cdim 128
#define Hdim 64

#define LOG2E 1.44269504f

// ---------------- scratch (static device globals) ----------------------------
__device__ __align__(128) __half g_q[(size_t)Nb * VQn * Hdim];   // pre-scaled by 0.125*log2e
__device__ __align__(128) __half g_k[(size_t)Nb * VKn * Hdim];
__device__ __align__(128) __half g_vt[(size_t)Nb * Cdim * VKn];  // V^T[n][dv][key]
// key-split partials: O [2][Nb*VQn][128] fp32, l [2][Nb*VQn]
#define HALF_ELEMS ((size_t)Nb * VQn * Cdim)   // 2,097,152
__device__ __align__(128) float g_op[2 * HALF_ELEMS];
__device__ __align__(128) float g_lp[2 * (size_t)Nb * VQn];

// ---------------- helpers ----------------------------------------------------
__device__ __forceinline__ u32 s2u(const void* p) {
    u32 a;
    asm("{ .reg .u64 t; cvta.to.shared.u64 t, %1; cvt.u32.u64 %0, t; }"
        : "=r"(a) : "l"(p));
    return a;
}
__device__ __forceinline__ void cp16(u32 dst, const void* src) {
    asm volatile("cp.async.cg.shared.global [%0], [%1], 16;"
                 :: "r"(dst), "l"(src) : "memory");
}
__device__ __forceinline__ void cp_commit() {
    asm volatile("cp.async.commit_group;" ::: "memory");
}
template <int N>
__device__ __forceinline__ void cp_wait() {
    asm volatile("cp.async.wait_group %0;" :: "n"(N) : "memory");
}
__device__ __forceinline__ u32 pk(float lo, float hi) {
    u32 d;
    asm("cvt.rn.f16x2.f32 %0, %1, %2;" : "=r"(d) : "f"(hi), "f"(lo));
    return d;
}
__device__ __forceinline__ void ldsm4(u32& r0, u32& r1, u32& r2, u32& r3, u32 a) {
    asm volatile("ldmatrix.sync.aligned.m8n8.x4.shared.b16 {%0,%1,%2,%3}, [%4];"
                 : "=r"(r0), "=r"(r1), "=r"(r2), "=r"(r3) : "r"(a));
}
__device__ __forceinline__ void ldsm4t(u32& r0, u32& r1, u32& r2, u32& r3, u32 a) {
    asm volatile("ldmatrix.sync.aligned.m8n8.x4.trans.shared.b16 {%0,%1,%2,%3}, [%4];"
                 : "=r"(r0), "=r"(r1), "=r"(r2), "=r"(r3) : "r"(a));
}
__device__ __forceinline__ void mma16816(float* d, u32 a0, u32 a1, u32 a2, u32 a3,
                                         u32 b0, u32 b1) {
    asm volatile(
        "mma.sync.aligned.m16n8k16.row.col.f32.f16.f16.f32 "
        "{%0,%1,%2,%3}, {%4,%5,%6,%7}, {%8,%9}, {%0,%1,%2,%3};"
        : "+f"(d[0]), "+f"(d[1]), "+f"(d[2]), "+f"(d[3])
        : "r"(a0), "r"(a1), "r"(a2), "r"(a3), "r"(b0), "r"(b1));
}
__device__ __forceinline__ float fexp2(float s) {
    float r;
    asm("ex2.approx.f32 %0, %1;" : "=f"(r) : "f"(fminf(s, 20.f)));
    return r;
}
__device__ __forceinline__ void sts128(u32 addr, u32 a, u32 b, u32 c, u32 d) {
    asm volatile("st.shared.v4.b32 [%0], {%1,%2,%3,%4};"
                 :: "r"(addr), "r"(a), "r"(b), "r"(c), "r"(d) : "memory");
}

// ---------------- projections via mma.sync (fused K+V task) -------------------
#define PTHREADS 256
#define PROWS    128
#define SM_A(c)    ((c) * 16384)            // 2 chunks x 16KB (A tile fp16)
#define PW_BASE    32768                     // W region base
#define PSMEM_TOTAL 81920                    // A 32KB + Wk 16KB + Wv 32KB
#define BSTB 272                             // V bounce row stride (bytes)

// load A[128 rows][128 k] fp32 -> fp16 swizzled smem (validated round-10 path)
__device__ __forceinline__ void load_A(const float* __restrict__ A, u32 sb,
                                       int r0, int tid) {
#pragma unroll
    for (int it = 0; it < 8; it++) {
        int g = tid + it * PTHREADS;
        int r = g >> 4;
        int k0 = (g & 15) * 8;
        const float* src = A + (size_t)(r0 + r) * 128 + k0;
        float4 v0 = *(const float4*)src;
        float4 v1 = *(const float4*)(src + 4);
        int ch = k0 >> 6, gran = (k0 & 63) >> 3;
        u32 addr = sb + SM_A(ch) + (u32)r * 128 + (u32)((gran ^ (r & 7)) << 4);
        sts128(addr, pk(v0.x, v0.y), pk(v0.z, v0.w), pk(v1.x, v1.y), pk(v1.z, v1.w));
    }
}

// load W[128][H] fp32 -> fp16 natural-layout swizzled smem at wbase
template <int H>
__device__ __forceinline__ void load_W(const float* __restrict__ W, u32 sb,
                                       u32 wbase, int tid) {
    constexpr int WGRAN = H / 8;
#pragma unroll
    for (int it = 0; it < (128 * WGRAN) / PTHREADS; it++) {
        int g = tid + it * PTHREADS;
        int kr = g / WGRAN;
        int hg = g % WGRAN;
        const float* src = W + (size_t)kr * H + hg * 8;
        float4 v0 = *(const float4*)src;
        float4 v1 = *(const float4*)(src + 4);
        int ch = hg >> 3, gran = hg & 7;
        u32 addr = sb + wbase + (u32)(ch * 16384) + (u32)kr * 128
                 + (u32)((gran ^ (kr & 7)) << 4);
        sts128(addr, pk(v0.x, v0.y), pk(v0.z, v0.w), pk(v1.x, v1.y), pk(v1.z, v1.w));
    }
}

// mma mainloop: M=16 per warp (8 warps = 128 rows), N=H, K=128 (ldsm.trans B)
template <int H>
__device__ __forceinline__ void proj_main(u32 sb, u32 wbase, int wid, int lane,
                                          float (&c)[H / 8][4]) {
    const u32 l7 = lane & 7;
    const u32 rowA = (l7 + 8 * ((lane >> 3) & 1)) * 128;
    const u32 bitA = (lane >> 4) & 1;
#pragma unroll
    for (int j = 0; j < H / 8; j++)
#pragma unroll
        for (int q = 0; q < 4; q++) c[j][q] = 0.f;
#pragma unroll
    for (int ks = 0; ks < 8; ks++) {
        const int ch = ks >> 2, kk = ks & 3;
        const u32 cszA = (((2 * kk + bitA) ^ l7) << 4);
        u32 a0, a1, a2, a3;
        ldsm4(a0, a1, a2, a3, sb + SM_A(ch) + (u32)(wid * 16) * 128 + rowA + cszA);
        const u32 wrowbase = (u32)(ks * 16) * 128 + rowA;
#pragma unroll
        for (int np = 0; np < H / 16; np++) {
            const int wch = (np * 16) >> 6;
            const u32 gb = (u32)((2 * np) & 7) + bitA;
            u32 b0, b1, b2, b3;
            ldsm4t(b0, b1, b2, b3,
                   sb + wbase + (u32)(wch * 16384) + wrowbase + ((gb ^ l7) << 4));
            mma16816(c[2 * np],     a0, a1, a2, a3, b0, b1);
            mma16816(c[2 * np + 1], a0, a1, a2, a3, b2, b3);
        }
    }
}

// row-major fp16 epilogue for H=64 outputs
__device__ __forceinline__ void store_rowmajor64(float (&c)[8][4], __half* o,
                                                 float scale, int r0, int wid,
                                                 int lane) {
    const int grow = r0 + wid * 16 + (lane >> 2);
    const int cb = 2 * (lane & 3);
#pragma unroll
    for (int j = 0; j < 8; j++) {
        *(u32*)(o + (size_t)grow * 64 + 8 * j + cb) =
            pk(c[j][0] * scale, c[j][1] * scale);
        *(u32*)(o + (size_t)(grow + 8) * 64 + 8 * j + cb) =
            pk(c[j][2] * scale, c[j][3] * scale);
    }
}

__global__ __launch_bounds__(PTHREADS)
void proj_mma(const float* __restrict__ x, const float* __restrict__ y,
              const float* __restrict__ Wq, const float* __restrict__ Wk,
              const float* __restrict__ Wv,
              __half* __restrict__ q, __half* __restrict__ k,
              __half* __restrict__ vt) {
    extern __shared__ char smx[];
    const u32 sb = s2u(smx);
    const int tid  = threadIdx.x;
    const int wid  = tid >> 5;
    const int lane = tid & 31;
    const int r0 = blockIdx.x * PROWS;

    if (blockIdx.y == 0) {
        // ---- Q task ----
        load_A(x, sb, r0, tid);
        load_W<64>(Wq, sb, PW_BASE, tid);
        __syncthreads();
        float c[8][4];
        proj_main<64>(sb, PW_BASE, wid, lane, c);
        store_rowmajor64(c, q, 0.125f * LOG2E, r0, wid, lane);
    } else {
        // ---- fused K+V task: load y tile ONCE ----
        load_A(y, sb, r0, tid);
        load_W<64>(Wk, sb, PW_BASE, tid);            // Wk at 32768 (16KB)
        load_W<128>(Wv, sb, PW_BASE + 16384, tid);   // Wv at 49152 (32KB)
        __syncthreads();

        // K projection
        {
            float c[8][4];
            proj_main<64>(sb, PW_BASE, wid, lane, c);
            store_rowmajor64(c, k, 1.0f, r0, wid, lane);
        }
        // V projection (transposed output via padded smem bounce)
        float c[16][4];
        proj_main<128>(sb, PW_BASE + 16384, wid, lane, c);

        __syncthreads();   // all warps done reading A/W smem (bounce overlays it)
        const int kr = wid * 16 + (lane >> 2);
        const int cb = 2 * (lane & 3);
#pragma unroll
        for (int j = 0; j < 16; j++) {
            *(u32*)(smx + kr * BSTB + (8 * j + cb) * 2) = pk(c[j][0], c[j][1]);
            *(u32*)(smx + (kr + 8) * BSTB + (8 * j + cb) * 2) = pk(c[j][2], c[j][3]);
        }
        __syncthreads();
        const int dv = tid >> 1;
        const int kh = tid & 1;
        const int nB = r0 >> 12;
        const int key0 = (r0 & 4095) + kh * 64;
        u32 buf[32];
#pragma unroll
        for (int i = 0; i < 32; i++) {
            u32 lo = *(const unsigned short*)(smx + (kh * 64 + 2 * i) * BSTB + dv * 2);
            u32 hi = *(const unsigned short*)(smx + (kh * 64 + 2 * i + 1) * BSTB + dv * 2);
            buf[i] = lo | (hi << 16);
        }
        __half* dst = vt + ((size_t)nB * 128 + dv) * 4096 + key0;
#pragma unroll
        for (int w = 0; w < 8; w++)
            *(uint4*)(dst + 8 * w) = make_uint4(buf[4 * w], buf[4 * w + 1],
                                                buf[4 * w + 2], buf[4 * w + 3]);
    }
}

// ------- flash attention: byte-identical to the round-14 winner ---------------
#define BM  128
#define BN  64
#define NTILES 32
#define FTHREADS 128

#define SM_Q       0
#define SM_KS(s)   (16384 + (s) * 24576)
#define SM_VS(s)   (SM_KS(s) + 8192)
#define SMEM_TOTAL 114688   // 16KB Q + 4 x 24KB stages; 2 CTAs = 224KB <= 228KB

__device__ __forceinline__ void load_kv(u32 sb, int stage, const char* kB,
                                        const char* vB, int kt, int tid) {
    const size_t krow = (size_t)kt * BN;
    const u32 kdst = sb + SM_KS(stage);
#pragma unroll
    for (int it = 0; it < 4; it++) {
        int i = tid + it * FTHREADS;
        u32 r = i >> 3, c = i & 7;
        cp16(kdst + r * 128 + ((c ^ (r & 7)) << 4), kB + (krow + r) * 128 + c * 16);
    }
    const u32 vdst = sb + SM_VS(stage);
#pragma unroll
    for (int it = 0; it < 8; it++) {
        int i = tid + it * FTHREADS;
        u32 r = i >> 3, c = i & 7;
        cp16(vdst + r * 128 + ((c ^ (r & 7)) << 4),
             vB + (size_t)r * 8192 + krow * 2 + c * 16);
    }
    cp_commit();
}

__global__ __launch_bounds__(FTHREADS, 2)
void flash_mma(const __half* __restrict__ Q, const __half* __restrict__ K,
               const __half* __restrict__ VT,
               float* __restrict__ opart, float* __restrict__ lpart) {
    extern __shared__ char smx[];
    const u32 sb = s2u(smx);
    const int tid  = threadIdx.x;
    const int wg   = tid >> 5;
    const int lane = tid & 31;
    const int n     = blockIdx.y;
    const int q0    = blockIdx.x * BM;
    const int khalf = blockIdx.z;
    const int kt0   = khalf * NTILES;

    const char* qB = (const char*)(Q + ((size_t)n * VQn + q0) * Hdim);
    const char* kB = (const char*)(K + (size_t)n * VKn * Hdim);
    const char* vB = (const char*)(VT + (size_t)n * Cdim * VKn);

#pragma unroll
    for (int it = 0; it < 8; it++) {
        int i = tid + it * FTHREADS;
        u32 r = i >> 3, c = i & 7;
        cp16(sb + SM_Q + r * 128 + ((c ^ (r & 7)) << 4), qB + r * 128 + c * 16);
    }
    cp_commit();
    load_kv(sb, 0, kB, vB, kt0, tid);
    load_kv(sb, 1, kB, vB, kt0 + 1, tid);
    load_kv(sb, 2, kB, vB, kt0 + 2, tid);
    cp_wait<2>();
    __syncthreads();

    const u32 l7 = lane & 7;
    const u32 rowA = (l7 + 8 * ((lane >> 3) & 1)) * 128;
    const u32 rowB = (l7 + 8 * ((lane >> 4) & 1)) * 128;
    const u32 bitA = (lane >> 4) & 1;
    const u32 bitB = (lane >> 3) & 1;
    u32 cswzA[4], cswzB[4];
#pragma unroll
    for (int kk = 0; kk < 4; kk++) {
        cswzA[kk] = (((2 * kk + bitA) ^ l7) << 4);
        cswzB[kk] = (((2 * kk + bitB) ^ l7) << 4);
    }

    u32 qf[4][8];
    {
        const u32 qb0 = sb + SM_Q + (u32)(wg * 32) * 128 + rowA;
#pragma unroll
        for (int kk = 0; kk < 4; kk++) {
            ldsm4(qf[kk][0], qf[kk][1], qf[kk][2], qf[kk][3], qb0 + cswzA[kk]);
            ldsm4(qf[kk][4], qf[kk][5], qf[kk][6], qf[kk][7], qb0 + 2048 + cswzA[kk]);
        }
    }

    float oacc[2][16][4];
#pragma unroll
    for (int m = 0; m < 2; m++)
#pragma unroll
        for (int v = 0; v < 16; v++)
#pragma unroll
            for (int c = 0; c < 4; c++) oacc[m][v][c] = 0.f;
    float lr[4] = {0.f, 0.f, 0.f, 0.f};

    for (int it = 0; it < NTILES; it++) {
        const int st = it & 3;
        if (it + 2 < NTILES) cp_wait<2>();
        else if (it + 1 < NTILES) cp_wait<1>();
        else cp_wait<0>();
        __syncthreads();
        if (it + 3 < NTILES) load_kv(sb, (it + 3) & 3, kB, vB, kt0 + it + 3, tid);

        u32 paf[4][8];
        const u32 kbase = sb + SM_KS(st) + rowB;
#pragma unroll
        for (int jp = 0; jp < 4; jp++) {
            float s00[4] = {0.f,0.f,0.f,0.f}, s01[4] = {0.f,0.f,0.f,0.f};
            float s10[4] = {0.f,0.f,0.f,0.f}, s11[4] = {0.f,0.f,0.f,0.f};
#pragma unroll
            for (int kk = 0; kk < 4; kk++) {
                u32 b0, b1, b2, b3;
                ldsm4(b0, b1, b2, b3, kbase + jp * 2048 + cswzB[kk]);
                mma16816(s00, qf[kk][0], qf[kk][1], qf[kk][2], qf[kk][3], b0, b1);
                mma16816(s01, qf[kk][0], qf[kk][1], qf[kk][2], qf[kk][3], b2, b3);
                mma16816(s10, qf[kk][4], qf[kk][5], qf[kk][6], qf[kk][7], b0, b1);
                mma16816(s11, qf[kk][4], qf[kk][5], qf[kk][6], qf[kk][7], b2, b3);
            }
            float e000 = fexp2(s00[0]), e001 = fexp2(s00[1]);
            float e002 = fexp2(s00[2]), e003 = fexp2(s00[3]);
            float e010 = fexp2(s01[0]), e011 = fexp2(s01[1]);
            float e012 = fexp2(s01[2]), e013 = fexp2(s01[3]);
            lr[0] += e000 + e001 + e010 + e011;
            lr[1] += e002 + e003 + e012 + e013;
            paf[jp][0] = pk(e000, e001);
            paf[jp][1] = pk(e002, e003);
            paf[jp][2] = pk(e010, e011);
            paf[jp][3] = pk(e012, e013);
            float e100 = fexp2(s10[0]), e101 = fexp2(s10[1]);
            float e102 = fexp2(s10[2]), e103 = fexp2(s10[3]);
            float e110 = fexp2(s11[0]), e111 = fexp2(s11[1]);
            float e112 = fexp2(s11[2]), e113 = fexp2(s11[3]);
            lr[2] += e100 + e101 + e110 + e111;
            lr[3] += e102 + e103 + e112 + e113;
            paf[jp][4] = pk(e100, e101);
            paf[jp][5] = pk(e102, e103);
            paf[jp][6] = pk(e110, e111);
            paf[jp][7] = pk(e112, e113);
        }

        const u32 vbase = sb + SM_VS(st) + rowB;
#pragma unroll
        for (int nvp = 0; nvp < 8; nvp++)
#pragma unroll
            for (int kk = 0; kk < 4; kk++) {
                u32 b0, b1, b2, b3;
                ldsm4(b0, b1, b2, b3, vbase + nvp * 2048 + cswzB[kk]);
                mma16816(oacc[0][2 * nvp],
                         paf[kk][0], paf[kk][1], paf[kk][2], paf[kk][3], b0, b1);
                mma16816(oacc[0][2 * nvp + 1],
                         paf[kk][0], paf[kk][1], paf[kk][2], paf[kk][3], b2, b3);
                mma16816(oacc[1][2 * nvp],
                         paf[kk][4], paf[kk][5], paf[kk][6], paf[kk][7], b0, b1);
                mma16816(oacc[1][2 * nvp + 1],
                         paf[kk][4], paf[kk][5], paf[kk][6], paf[kk][7], b2, b3);
            }
    }

#pragma unroll
    for (int d = 1; d < 4; d <<= 1)
#pragma unroll
        for (int i = 0; i < 4; i++)
            lr[i] += __shfl_xor_sync(0xffffffffu, lr[i], d);

    float* opb = opart + (size_t)khalf * HALF_ELEMS;
    float* lpb = lpart + (size_t)khalf * (Nb * VQn);
    const int cl = 2 * (lane & 3);
#pragma unroll
    for (int m = 0; m < 2; m++) {
        const int gr = q0 + wg * 32 + m * 16 + (lane >> 2);
        const size_t rowg = (size_t)n * VQn + gr;
        if ((lane & 3) == 0) {
            lpb[rowg]     = lr[2 * m];
            lpb[rowg + 8] = lr[2 * m + 1];
        }
#pragma unroll
        for (int v = 0; v < 16; v++) {
            *(float2*)&opb[rowg * 128 + v * 8 + cl] =
                make_float2(oacc[m][v][0], oacc[m][v][1]);
            *(float2*)&opb[(rowg + 8) * 128 + v * 8 + cl] =
                make_float2(oacc[m][v][2], oacc[m][v][3]);
        }
    }
}

// ---------------- combine: out = (O0+O1) / (l0+l1) ---------------------------
__global__ __launch_bounds__(256)
void combine(const float* __restrict__ opart, const float* __restrict__ lpart,
             float* __restrict__ out) {
    const size_t i = (size_t)blockIdx.x * 256 + threadIdx.x;
    const size_t row = i >> 5;
    const float inv = 1.f / (lpart[row] + lpart[(size_t)Nb * VQn + row]);
    float4 a = *(const float4*)(opart + 4 * i);
    float4 b = *(const float4*)(opart + HALF_ELEMS + 4 * i);
    float4 o;
    o.x = (a.x + b.x) * inv;
    o.y = (a.y + b.y) * inv;
    o.z = (a.z + b.z) * inv;
    o.w = (a.w + b.w) * inv;
    *(float4*)(out + 4 * i) = o;
}

// ---------------- launch ------------------------------------------------------
extern "C" void kernel_launch(void* const* d_in, const int* in_sizes, int n_in,
                              void* d_out, int out_size) {
    (void)in_sizes; (void)n_in; (void)out_size;
    const float* x  = (const float*)d_in[0];
    const float* y  = (const float*)d_in[1];
    const float* Wq = (const float*)d_in[2];
    const float* Wk = (const float*)d_in[3];
    const float* Wv = (const float*)d_in[4];
    float* out = (float*)d_out;

    __half *qp, *kp, *vtp;
    float *opp, *lpp;
    cudaGetSymbolAddress((void**)&qp, g_q);
    cudaGetSymbolAddress((void**)&kp, g_k);
    cudaGetSymbolAddress((void**)&vtp, g_vt);
    cudaGetSymbolAddress((void**)&opp, g_op);
    cudaGetSymbolAddress((void**)&lpp, g_lp);

    cudaFuncSetAttribute(proj_mma,
                         cudaFuncAttributeMaxDynamicSharedMemorySize, PSMEM_TOTAL);
    cudaFuncSetAttribute(flash_mma,
                         cudaFuncAttributeMaxDynamicSharedMemorySize, SMEM_TOTAL);

    dim3 pgrid(Nb * VQn / PROWS, 2);
    proj_mma<<<pgrid, PTHREADS, PSMEM_TOTAL>>>(x, y, Wq, Wk, Wv, qp, kp, vtp);

    dim3 grid(VQn / BM, Nb, 2);
    flash_mma<<<grid, FTHREADS, SMEM_TOTAL>>>(qp, kp, vtp, opp, lpp);

    combine<<<(int)(HALF_ELEMS / 4 / 256), 256>>>(opp, lpp, out);
}